// round 9
// baseline (speedup 1.0000x reference)
#include <cuda_runtime.h>
#include <cuda_fp16.h>
#include <cstdint>

// ToeplitzLinear: D[m,n] = sum_k X[m,k] * vals[4095 - n + k]
// R9: fp16 m16n8k16, BK=128 (32 iters), 3-stage 32KB cp.async ring,
// vals-prepass fused into X-prepass (2 launches/call -> ncu catches main).

#define M_DIM 8192
#define N_DIM 4096
#define K_DIM 4096
#define BM 128
#define BN 128
#define BK 128
#define NITER (K_DIM / BK)       // 32
#define THREADS 256

#define A_STAGE_BYTES 32768      // 8 rb x 8 cb x 32 lanes x 16B
#define SMEM_TOTAL (3 * A_STAGE_BYTES)   // 98304

// X as fp16 in m16n8k16-fragment order:
//   word idx = (rb*256 + cb)*128 + lane*4 + j,  rb=m>>4, cb=k>>4
__device__ uint32_t g_xh[(size_t)M_DIM * K_DIM / 2];
__device__ uint32_t g_v2h[8192];   // g_v2h[i] = half2(w[i], w[i+1]), w = fp16(vals)

__device__ __forceinline__ uint32_t smem_u32(const void* p) {
    uint32_t a;
    asm("{ .reg .u64 t; cvta.to.shared.u64 t, %1; cvt.u32.u64 %0, t; }"
        : "=r"(a) : "l"(p));
    return a;
}
__device__ __forceinline__ void cp16(uint32_t saddr, const void* g) {
    asm volatile("cp.async.cg.shared.global [%0], [%1], 16;"
                 :: "r"(saddr), "l"(g) : "memory");
}
__device__ __forceinline__ void cp_commit() {
    asm volatile("cp.async.commit_group;" ::: "memory");
}
template <int N>
__device__ __forceinline__ void cp_wait() {
    asm volatile("cp.async.wait_group %0;" :: "n"(N) : "memory");
}
__device__ __forceinline__ void mma_fp16(float c[4], uint32_t a0, uint32_t a1,
                                         uint32_t a2, uint32_t a3,
                                         uint32_t b0, uint32_t b1) {
    asm volatile(
        "mma.sync.aligned.m16n8k16.row.col.f32.f16.f16.f32 "
        "{%0,%1,%2,%3}, {%4,%5,%6,%7}, {%8,%9}, {%0,%1,%2,%3};"
        : "+f"(c[0]), "+f"(c[1]), "+f"(c[2]), "+f"(c[3])
        : "r"(a0), "r"(a1), "r"(a2), "r"(a3), "r"(b0), "r"(b1));
}

// ---- pre-pass: X -> fp16 fragment-shuffled; block(0,0) also builds g_v2h ----
__global__ void __launch_bounds__(128) cvt_x_kernel(const float* __restrict__ x,
                                                    const float* __restrict__ v) {
    __shared__ float sm[16 * 128];
    const int tid = threadIdx.x;
    const int rb = blockIdx.y;            // 0..511 (16-row block)
    const int c0 = blockIdx.x * 128;      // 128-col chunk (8 cbs)

    if (blockIdx.x == 0 && blockIdx.y == 0) {
        for (int i = tid; i < 8192; i += 128) {
            float a = (i < 8191) ? v[i] : 0.0f;
            float b = (i + 1 < 8191) ? v[i + 1] : 0.0f;
            __half2 h = __floats2half2_rn(a, b);
            g_v2h[i] = *reinterpret_cast<uint32_t*>(&h);
        }
    }
#pragma unroll
    for (int i = 0; i < 4; i++) {
        const int f = tid + 128 * i;      // float4 id 0..511
        const int r = f >> 5;
        const int cq = f & 31;
        float4 vv = *reinterpret_cast<const float4*>(
            x + (size_t)(rb * 16 + r) * K_DIM + c0 + cq * 4);
        float* s = sm + r * 128 + cq * 4;
        s[0] = vv.x; s[1] = vv.y; s[2] = vv.z; s[3] = vv.w;
    }
    __syncthreads();
#pragma unroll
    for (int i = 0; i < 4; i++) {
        const int p = tid + 128 * i;      // 0..511
        const int cbL = p >> 6;           // 0..7
        const int pw = p & 63;
        const int widx = pw * 2;          // even word index
        const int lane = widx >> 2;
        const int j = widx & 3;           // 0 or 2
        const int g = lane >> 2;
        const int tig = lane & 3;
        const int k = cbL * 16 + 2 * tig + (j >> 1) * 8;
        __half2 lo = __floats2half2_rn(sm[g * 128 + k], sm[g * 128 + k + 1]);
        __half2 hi = __floats2half2_rn(sm[(g + 8) * 128 + k], sm[(g + 8) * 128 + k + 1]);
        uint2 u;
        u.x = *reinterpret_cast<uint32_t*>(&lo);
        u.y = *reinterpret_cast<uint32_t*>(&hi);
        *reinterpret_cast<uint2*>(
            g_xh + ((size_t)rb * 256 + (c0 >> 4) + cbL) * 128 + widx) = u;
    }
}

__device__ __forceinline__ void issue_a(int u, int tid, uint32_t sb, int m0) {
    const uint32_t sbase = sb + (u % 3) * A_STAGE_BYTES;
#pragma unroll
    for (int i = 0; i < 8; i++) {
        const int cid = tid + THREADS * i;        // 0..2047 16B-chunks
        const int rbL = cid >> 8;                 // 0..7
        const int cbL = (cid >> 5) & 7;           // 0..7
        const int ch = cid & 31;
        const void* g = g_xh +
            ((size_t)((m0 >> 4) + rbL) * 256 + 8 * u + cbL) * 128 + ch * 4;
        cp16(sbase + cid * 16, g);
    }
}

__global__ void __launch_bounds__(THREADS, 2)
toeplitz_mma_kernel(float* __restrict__ out) {
    extern __shared__ char smem[];
    const uint32_t sb = smem_u32(smem);
    const int tid = threadIdx.x;
    const int wid = tid >> 5;
    const int lane = tid & 31;
    const int g = lane >> 2;
    const int tig = lane & 3;
    const int warpM = wid & 3;
    const int warpN = wid >> 2;

    const int n0 = blockIdx.x * BN;   // n fastest -> X tile L2 reuse
    const int m0 = blockIdx.y * BM;
    const int vbase = 3968 - n0;      // window t = g_v2h[vbase + 128t + s]

    float acc[2][8][4];
#pragma unroll
    for (int mm = 0; mm < 2; mm++)
#pragma unroll
        for (int nn = 0; nn < 8; nn++)
#pragma unroll
            for (int r = 0; r < 4; r++) acc[mm][nn][r] = 0.0f;

    issue_a(0, tid, sb, m0);
    cp_commit();
    issue_a(1, tid, sb, m0);
    cp_commit();

    // B-frag: b0 = window[Q + 8e], b1 = window[Q + 8e + 8], e = 2ks-nn+7 in
    // [0,21]; Q in [0,77]; max global pair idx = 3968+3968+253 = 8189 < 8192
    const int Q = 2 * tig - g + 71 - warpN * 64;

#pragma unroll 1
    for (int t = 0; t < NITER; t++) {
        cp_wait<1>();
        __syncthreads();

        // 23 diagonal B fragments (L1-resident LDG.32 of half2 pairs)
        const uint32_t* vp = g_v2h + vbase + 128 * t + Q;
        uint32_t Bf[23];
#pragma unroll
        for (int e = 0; e < 23; e++) Bf[e] = __ldg(vp + 8 * e);

        if (t + 2 < NITER) issue_a(t + 2, tid, sb, m0);
        cp_commit();

        const char* sA = smem + (t % 3) * A_STAGE_BYTES;
#pragma unroll
        for (int ks = 0; ks < 8; ks++) {
            uint4 A0 = *reinterpret_cast<const uint4*>(
                sA + (((warpM * 2 + 0) * 8 + ks) * 32 + lane) * 16);
            uint4 A1 = *reinterpret_cast<const uint4*>(
                sA + (((warpM * 2 + 1) * 8 + ks) * 32 + lane) * 16);
#pragma unroll
            for (int nn = 0; nn < 8; nn++) {
                const int e = 2 * ks - nn + 7;
                mma_fp16(acc[0][nn], A0.x, A0.y, A0.z, A0.w, Bf[e], Bf[e + 1]);
                mma_fp16(acc[1][nn], A1.x, A1.y, A1.z, A1.w, Bf[e], Bf[e + 1]);
            }
        }
    }

    // epilogue: c0/c1 adjacent columns -> float2 stores
#pragma unroll
    for (int mm = 0; mm < 2; mm++) {
        const int row = m0 + warpM * 32 + mm * 16 + g;
#pragma unroll
        for (int nn = 0; nn < 8; nn++) {
            const int col = n0 + warpN * 64 + nn * 8 + tig * 2;
            *reinterpret_cast<float2*>(out + (size_t)row * N_DIM + col) =
                make_float2(acc[mm][nn][0], acc[mm][nn][1]);
            *reinterpret_cast<float2*>(out + (size_t)(row + 8) * N_DIM + col) =
                make_float2(acc[mm][nn][2], acc[mm][nn][3]);
        }
    }
}

extern "C" void kernel_launch(void* const* d_in, const int* in_sizes, int n_in,
                              void* d_out, int out_size) {
    const float* x    = (const float*)d_in[0];
    const float* vals = (const float*)d_in[1];
    float* out        = (float*)d_out;

    static int attr_set = 0;
    if (!attr_set) {
        cudaFuncSetAttribute(toeplitz_mma_kernel,
                             cudaFuncAttributeMaxDynamicSharedMemorySize,
                             SMEM_TOTAL);
        attr_set = 1;
    }

    cvt_x_kernel<<<dim3(K_DIM / 128, M_DIM / 16), 128>>>(x, vals);

    dim3 grid(N_DIM / BN, M_DIM / BM);   // 32 x 64
    toeplitz_mma_kernel<<<grid, THREADS, SMEM_TOTAL>>>(out);
}

// round 10
// speedup vs baseline: 1.0457x; 1.0457x over previous
#include <cuda_runtime.h>
#include <cuda_fp16.h>
#include <cstdint>

// ToeplitzLinear: D[m,n] = sum_k X[m,k] * vals[4095 - n + k]
// R10: barrier-free mainloop. A fragments loaded directly from the
// fragment-shuffled fp16 gmem scratch (coalesced LDG.128, L2-resident);
// the CTA's entire vals pair-window (4222 pairs, 16.9KB) is staged in smem
// once at kernel start -> B frags are LDS.32. No cp.async, no per-iter sync.

#define M_DIM 8192
#define N_DIM 4096
#define K_DIM 4096
#define BM 128
#define BN 128
#define BK 64
#define NITER (K_DIM / BK)       // 64
#define THREADS 256

#define VWIN_WORDS 4224          // >= 64*63 + 77 + 112 + 1, 16B-aligned

// X as fp16 in m16n8k16-fragment order:
//   word idx = (rb*256 + cb)*128 + lane*4 + j,  rb=m>>4, cb=k>>4
__device__ uint32_t g_xh[(size_t)M_DIM * K_DIM / 2];
__device__ uint32_t g_v2h[8192];   // g_v2h[i] = half2(w[i], w[i+1]), w = fp16(vals)

__device__ __forceinline__ void mma_fp16(float c[4], uint32_t a0, uint32_t a1,
                                         uint32_t a2, uint32_t a3,
                                         uint32_t b0, uint32_t b1) {
    asm volatile(
        "mma.sync.aligned.m16n8k16.row.col.f32.f16.f16.f32 "
        "{%0,%1,%2,%3}, {%4,%5,%6,%7}, {%8,%9}, {%0,%1,%2,%3};"
        : "+f"(c[0]), "+f"(c[1]), "+f"(c[2]), "+f"(c[3])
        : "r"(a0), "r"(a1), "r"(a2), "r"(a3), "r"(b0), "r"(b1));
}

// ---- pre-pass: X -> fp16 fragment-shuffled; block(0,0) also builds g_v2h ----
__global__ void __launch_bounds__(128) cvt_x_kernel(const float* __restrict__ x,
                                                    const float* __restrict__ v) {
    __shared__ float sm[16 * 128];
    const int tid = threadIdx.x;
    const int rb = blockIdx.y;            // 0..511 (16-row block)
    const int c0 = blockIdx.x * 128;      // 128-col chunk (8 cbs)

    if (blockIdx.x == 0 && blockIdx.y == 0) {
        for (int i = tid; i < 8192; i += 128) {
            float a = (i < 8191) ? v[i] : 0.0f;
            float b = (i + 1 < 8191) ? v[i + 1] : 0.0f;
            __half2 h = __floats2half2_rn(a, b);
            g_v2h[i] = *reinterpret_cast<uint32_t*>(&h);
        }
    }
#pragma unroll
    for (int i = 0; i < 4; i++) {
        const int f = tid + 128 * i;      // float4 id 0..511
        const int r = f >> 5;
        const int cq = f & 31;
        float4 vv = *reinterpret_cast<const float4*>(
            x + (size_t)(rb * 16 + r) * K_DIM + c0 + cq * 4);
        float* s = sm + r * 128 + cq * 4;
        s[0] = vv.x; s[1] = vv.y; s[2] = vv.z; s[3] = vv.w;
    }
    __syncthreads();
#pragma unroll
    for (int i = 0; i < 4; i++) {
        const int p = tid + 128 * i;      // 0..511
        const int cbL = p >> 6;           // 0..7
        const int pw = p & 63;
        const int widx = pw * 2;          // even word index
        const int lane = widx >> 2;
        const int j = widx & 3;           // 0 or 2
        const int g = lane >> 2;
        const int tig = lane & 3;
        const int k = cbL * 16 + 2 * tig + (j >> 1) * 8;
        __half2 lo = __floats2half2_rn(sm[g * 128 + k], sm[g * 128 + k + 1]);
        __half2 hi = __floats2half2_rn(sm[(g + 8) * 128 + k], sm[(g + 8) * 128 + k + 1]);
        uint2 u;
        u.x = *reinterpret_cast<uint32_t*>(&lo);
        u.y = *reinterpret_cast<uint32_t*>(&hi);
        *reinterpret_cast<uint2*>(
            g_xh + ((size_t)rb * 256 + (c0 >> 4) + cbL) * 128 + widx) = u;
    }
}

__global__ void __launch_bounds__(THREADS, 2)
toeplitz_mma_kernel(float* __restrict__ out) {
    __shared__ uint32_t sv[VWIN_WORDS];   // CTA-lifetime vals pair window

    const int tid = threadIdx.x;
    const int wid = tid >> 5;
    const int lane = tid & 31;
    const int g = lane >> 2;
    const int tig = lane & 3;
    const int warpM = wid & 3;
    const int warpN = wid >> 2;

    const int n0 = blockIdx.x * BN;   // n fastest -> X slice L2 reuse
    const int m0 = blockIdx.y * BM;
    const int vbase = 3968 - n0;      // pair window base (0..3968, 16B-aligned)

    // ---- stage the whole vals window once (4224 words = 264 uint4) ----
    {
        const uint4* src = reinterpret_cast<const uint4*>(g_v2h + vbase);
        uint4* dst = reinterpret_cast<uint4*>(sv);
        for (int i = tid; i < VWIN_WORDS / 4; i += THREADS) {
            // global uint4 idx max: (vbase>>2) + 1055 <= 992+1055 = 2047 ✓
            dst[i] = src[i];
        }
    }

    float acc[2][8][4];
#pragma unroll
    for (int mm = 0; mm < 2; mm++)
#pragma unroll
        for (int nn = 0; nn < 8; nn++)
#pragma unroll
            for (int r = 0; r < 4; r++) acc[mm][nn][r] = 0.0f;

    __syncthreads();   // the only barrier before the epilogue

    // B-frag: b0 = sv[64t + Q + 8e], b1 = +8; e = 2ks-nn+7 in [0,13]
    const int Q = 2 * tig - g + 71 - warpN * 64;   // in [0,77]

    // A row-block bases for this warp (fragment-major gmem)
    const uint4* ap0 = reinterpret_cast<const uint4*>(
        g_xh + ((size_t)((m0 >> 4) + warpM * 2 + 0) * 256) * 128) + lane;
    const uint4* ap1 = reinterpret_cast<const uint4*>(
        g_xh + ((size_t)((m0 >> 4) + warpM * 2 + 1) * 256) * 128) + lane;

#pragma unroll 1
    for (int t = 0; t < NITER; t++) {
        // 15 diagonal B fragments from smem window
        const uint32_t* vp = sv + 64 * t + Q;
        uint32_t Bf[15];
#pragma unroll
        for (int e = 0; e < 15; e++) Bf[e] = vp[8 * e];

        // A fragments: 8 coalesced LDG.128 (L2-resident scratch)
        uint4 a0[4], a1[4];
#pragma unroll
        for (int ks = 0; ks < 4; ks++) {
            a0[ks] = __ldg(ap0 + (size_t)(4 * t + ks) * 32);
            a1[ks] = __ldg(ap1 + (size_t)(4 * t + ks) * 32);
        }

#pragma unroll
        for (int ks = 0; ks < 4; ks++) {
#pragma unroll
            for (int nn = 0; nn < 8; nn++) {
                const int e = 2 * ks - nn + 7;
                mma_fp16(acc[0][nn], a0[ks].x, a0[ks].y, a0[ks].z, a0[ks].w,
                         Bf[e], Bf[e + 1]);
                mma_fp16(acc[1][nn], a1[ks].x, a1[ks].y, a1[ks].z, a1[ks].w,
                         Bf[e], Bf[e + 1]);
            }
        }
    }

    // epilogue: c0/c1 adjacent columns -> float2 stores
#pragma unroll
    for (int mm = 0; mm < 2; mm++) {
        const int row = m0 + warpM * 32 + mm * 16 + g;
#pragma unroll
        for (int nn = 0; nn < 8; nn++) {
            const int col = n0 + warpN * 64 + nn * 8 + tig * 2;
            *reinterpret_cast<float2*>(out + (size_t)row * N_DIM + col) =
                make_float2(acc[mm][nn][0], acc[mm][nn][1]);
            *reinterpret_cast<float2*>(out + (size_t)(row + 8) * N_DIM + col) =
                make_float2(acc[mm][nn][2], acc[mm][nn][3]);
        }
    }
}

extern "C" void kernel_launch(void* const* d_in, const int* in_sizes, int n_in,
                              void* d_out, int out_size) {
    const float* x    = (const float*)d_in[0];
    const float* vals = (const float*)d_in[1];
    float* out        = (float*)d_out;

    cvt_x_kernel<<<dim3(K_DIM / 128, M_DIM / 16), 128>>>(x, vals);

    dim3 grid(N_DIM / BN, M_DIM / BM);   // 32 x 64
    toeplitz_mma_kernel<<<grid, THREADS>>>(out);
}